// round 12
// baseline (speedup 1.0000x reference)
#include <cuda_runtime.h>
#include <stdint.h>

#define WW 2048
#define STR 8
#define NWW 255
#define P_TOT 32385          /* 127 * 255 */
#define MARGIN_F 1e-4f
#define FULL 0xffffffffu
#define NSLOT 32

__device__ double   g_loss_slot[NSLOT];   // zero-init; reset by finalizer
__device__ double   g_used_slot[NSLOT];
__device__ unsigned g_done = 0u;

// bank-conflict-free granule swizzle: 16B granule g -> g ^ ((g>>2)&7)
__device__ __forceinline__ int swz(int g) { return g ^ ((g >> 2) & 7); }

// sel iff sign(dt) != sign(dp): signbit XOR + the dt==0 self-pair case
__device__ __forceinline__ bool sel_pair(float dt, float dp) {
    return (((__float_as_uint(dt) ^ __float_as_uint(dp)) >> 31) != 0u)
           | (dt == 0.0f);
}

// ---------------------------------------------------------------------------
// ONE WARP PER BLOCK, one patch per block: eliminates intra-block load
// imbalance between the K<=128 fast path (~0.52 of patches) and the K>128
// path — block time is now per-patch time and the CTA scheduler packs them.
//   token = (noise_bits & 0xFFFFFF00) | elem_idx  (masked, < 0xFF000000)
//         =  0xFF000000 | elem_idx                (unmasked -> sorts last)
// ---------------------------------------------------------------------------
__global__ __launch_bounds__(32) void patch_loss_kernel(
    const float* __restrict__ pred,
    const float* __restrict__ target,
    const uint8_t* __restrict__ mask_raw,
    const float* __restrict__ noise,
    float* __restrict__ out)
{
    __shared__ float2   s_pt [256];      // swizzled (pred,target)
    __shared__ uint8_t  s_m  [256];
    __shared__ uint32_t s_tok[128];      // compacted tokens (path A)

    const int lane = threadIdx.x;
    const int p    = blockIdx.x;

    // ---- mask dtype detect on first 1KB (L2-resident for all blocks) ----
    int mode;
    {
        const uint32_t* w = (const uint32_t*)mask_raw;
        uint32_t acc_or = 0; bool gt1 = false;
        #pragma unroll
        for (int i = 0; i < 8; i++) {
            const uint32_t x = __ldg(w + lane + 32 * i);
            acc_or |= x; gt1 |= (x > 1u);
        }
        const unsigned bb = __ballot_sync(FULL, (acc_or & 0xFEFEFEFEu) != 0);
        const unsigned bg = __ballot_sync(FULL, gt1);
        mode = bb ? 1 : (bg ? 0 : 2);    // f32 : u8 : i32
    }

    const int pi = p / NWW;
    const int pj = p - pi * NWW;
    const int br = pi * STR;
    const int bc = pj * STR;

    const int e0    = lane << 3;             // this thread's 8 elements
    const int a     = lane >> 1;             // patch row
    const int gbase = (br + a) * WW + bc + ((lane & 1) << 3);

    // ---- vectorized loads ----
    const float4 p0 = __ldg((const float4*)(pred + gbase));
    const float4 p1 = __ldg((const float4*)(pred + gbase) + 1);
    const float4 t0 = __ldg((const float4*)(target + gbase));
    const float4 t1 = __ldg((const float4*)(target + gbase) + 1);

    // swizzled conflict-free STS.128: granule g = 4*lane + i
    {
        float4* base = (float4*)&s_pt[0];
        const int g0 = lane << 2;
        base[swz(g0 + 0)] = make_float4(p0.x, t0.x, p0.y, t0.y);
        base[swz(g0 + 1)] = make_float4(p0.z, t0.z, p0.w, t0.w);
        base[swz(g0 + 2)] = make_float4(p1.x, t1.x, p1.y, t1.y);
        base[swz(g0 + 3)] = make_float4(p1.z, t1.z, p1.w, t1.w);
    }

    uint32_t mbits;                          // bit r = element e0+r masked
    if (mode == 0) {
        const uint2 mb = __ldg((const uint2*)(mask_raw + gbase));
        uint32_t b = 0;
        #pragma unroll
        for (int r = 0; r < 4; r++) b |= ((mb.x >> (8 * r)) & 1u) << r;
        #pragma unroll
        for (int r = 0; r < 4; r++) b |= ((mb.y >> (8 * r)) & 1u) << (4 + r);
        mbits = b;
    } else if (mode == 1) {
        const float4 m0 = __ldg((const float4*)((const float*)mask_raw + gbase));
        const float4 m1 = __ldg((const float4*)((const float*)mask_raw + gbase) + 1);
        mbits = (m0.x != 0.f) | ((m0.y != 0.f) << 1) | ((m0.z != 0.f) << 2) |
                ((m0.w != 0.f) << 3) | ((m1.x != 0.f) << 4) | ((m1.y != 0.f) << 5) |
                ((m1.z != 0.f) << 6) | ((m1.w != 0.f) << 7);
    } else {
        const uint4 m0 = __ldg((const uint4*)((const uint32_t*)mask_raw + gbase));
        const uint4 m1 = __ldg((const uint4*)((const uint32_t*)mask_raw + gbase) + 1);
        mbits = (m0.x != 0) | ((m0.y != 0) << 1) | ((m0.z != 0) << 2) |
                ((m0.w != 0) << 3) | ((m1.x != 0) << 4) | ((m1.y != 0) << 5) |
                ((m1.z != 0) << 6) | ((m1.w != 0) << 7);
    }

    const float4 n0 = __ldg((const float4*)(noise + (size_t)p * 256 + e0));
    const float4 n1 = __ldg((const float4*)(noise + (size_t)p * 256 + e0) + 1);
    const float nz[8] = {n0.x, n0.y, n0.z, n0.w, n1.x, n1.y, n1.z, n1.w};

    uint32_t tok[8];
    #pragma unroll
    for (int r = 0; r < 8; r++) {
        const uint32_t kb = __float_as_uint(nz[r]) & 0xFFFFFF00u;
        tok[r] = ((mbits >> r) & 1u) ? (kb | (uint32_t)(e0 + r))
                                     : (0xFF000000u | (uint32_t)(e0 + r));
    }

    // ---- ranks of masked elements (element order == 8*lane + r) ----
    const int cnt = __popc(mbits);
    int inc = cnt;
    #pragma unroll
    for (int o = 1; o < 32; o <<= 1) {
        const int t = __shfl_up_sync(FULL, inc, o);
        if (lane >= o) inc += t;
    }
    const int K = __shfl_sync(FULL, inc, 31);   // warp-uniform
    const bool pathA = (K <= 128);
    const int base = inc - cnt;

    // compaction with independent offsets
    #pragma unroll
    for (int r = 0; r < 8; r++) {
        if ((mbits >> r) & 1u) {
            const int off = base + __popc(mbits & ((1u << r) - 1u));
            s_m[off] = (uint8_t)(e0 + r);
            if (pathA) s_tok[off] = tok[r];
        }
    }
    if (pathA) {
        for (int v = K + lane; v < 128; v += 32)
            s_tok[v] = 0xFFFFFFFFu;
    }
    __syncwarp();

    const float2* ptbase = &s_pt[0];
    float loss = 0.f;
    int   hit  = 0;

    if (pathA) {
        // ==== 128-wide sort over positions v = 4*lane + r ====
        uint32_t t4[4];
        {
            const uint4 ld = *(const uint4*)&s_tok[lane << 2];
            t4[0] = ld.x; t4[1] = ld.y; t4[2] = ld.z; t4[3] = ld.w;
        }
        #pragma unroll
        for (int k = 2; k <= 128; k <<= 1) {
            #pragma unroll
            for (int j = k >> 1; j >= 1; j >>= 1) {
                if (j >= 4) {
                    const int jl = j >> 2;
                    const bool up = ((lane & (k >> 2)) == 0);
                    const bool tm = (up == ((lane & jl) == 0));
                    #pragma unroll
                    for (int r = 0; r < 4; r++) {
                        const uint32_t o = __shfl_xor_sync(FULL, t4[r], jl);
                        t4[r] = tm ? min(t4[r], o) : max(t4[r], o);
                    }
                } else {
                    #pragma unroll
                    for (int r = 0; r < 4; r++) {
                        if ((r & j) == 0) {
                            const int r2 = r | j;
                            const bool up = (k < 4) ? ((r & k) == 0)
                                                    : ((lane & (k >> 2)) == 0);
                            const uint32_t A = t4[r], B = t4[r2];
                            t4[r]  = up ? min(A, B) : max(A, B);
                            t4[r2] = up ? max(A, B) : min(A, B);
                        }
                    }
                }
            }
        }
        #pragma unroll
        for (int r = 0; r < 4; r++) {
            const int v = (lane << 2) + r;
            if (v < K) {
                const int bI = (int)(t4[r] & 0xFFu);
                const int aI = (int)s_m[v];
                const float2 A = ptbase[(swz(aI >> 1) << 1) | (aI & 1)];
                const float2 B = ptbase[(swz(bI >> 1) << 1) | (bI & 1)];
                const float dt = A.y - B.y;
                const float dp = A.x - B.x + MARGIN_F;
                if (sel_pair(dt, dp)) { hit++; loss += fabsf(dp); }
            }
        }
    } else {
        // ==== 256-wide sort over positions v = 8*lane + r ====
        #pragma unroll
        for (int k = 2; k <= 256; k <<= 1) {
            #pragma unroll
            for (int j = k >> 1; j >= 1; j >>= 1) {
                if (j >= 8) {
                    const int jl = j >> 3;
                    const bool up = ((lane & (k >> 3)) == 0);
                    const bool tm = (up == ((lane & jl) == 0));
                    #pragma unroll
                    for (int r = 0; r < 8; r++) {
                        const uint32_t o = __shfl_xor_sync(FULL, tok[r], jl);
                        tok[r] = tm ? min(tok[r], o) : max(tok[r], o);
                    }
                } else {
                    #pragma unroll
                    for (int r = 0; r < 8; r++) {
                        if ((r & j) == 0) {
                            const int r2 = r | j;
                            const bool up = (k < 8) ? ((r & k) == 0)
                                                    : ((lane & (k >> 3)) == 0);
                            const uint32_t A = tok[r], B = tok[r2];
                            tok[r]  = up ? min(A, B) : max(A, B);
                            tok[r2] = up ? max(A, B) : min(A, B);
                        }
                    }
                }
            }
        }
        #pragma unroll
        for (int r = 0; r < 8; r++) {
            const int v = e0 + r;
            if (v < K) {
                const int bI = (int)(tok[r] & 0xFFu);
                const int aI = (int)s_m[v];
                const float2 A = ptbase[(swz(aI >> 1) << 1) | (aI & 1)];
                const float2 B = ptbase[(swz(bI >> 1) << 1) | (bI & 1)];
                const float dt = A.y - B.y;
                const float dp = A.x - B.x + MARGIN_F;
                if (sel_pair(dt, dp)) { hit++; loss += fabsf(dp); }
            }
        }
    }

    hit = __reduce_add_sync(FULL, hit);
    #pragma unroll
    for (int o = 16; o; o >>= 1)
        loss += __shfl_xor_sync(FULL, loss, o);

    // ---- per-block accumulation into 32 slots; last block finalizes ----
    if (lane == 0) {
        const int slot = p & (NSLOT - 1);
        if (K > 0) {
            atomicAdd(&g_loss_slot[slot], (double)(loss / (float)hit));
            atomicAdd(&g_used_slot[slot], 1.0);
        }
        __threadfence();
        const unsigned ticket = atomicAdd(&g_done, 1u);
        if (ticket == (unsigned)(gridDim.x - 1)) {
            double ls = 0.0, us = 0.0;
            #pragma unroll
            for (int s = 0; s < NSLOT; s++) {
                ls += atomicAdd(&g_loss_slot[s], 0.0);
                us += atomicAdd(&g_used_slot[s], 0.0);
            }
            out[0] = (float)(ls / us);
            #pragma unroll
            for (int s = 0; s < NSLOT; s++) {   // reset for next graph replay
                g_loss_slot[s] = 0.0;
                g_used_slot[s] = 0.0;
            }
            __threadfence();
            g_done = 0u;
        }
    }
}

// ---------------------------------------------------------------------------
extern "C" void kernel_launch(void* const* d_in, const int* in_sizes, int n_in,
                              void* d_out, int out_size) {
    const float*   pred   = (const float*)d_in[0];
    const float*   target = (const float*)d_in[1];
    const uint8_t* mask   = (const uint8_t*)d_in[2];
    const float*   noise  = (const float*)d_in[3];

    patch_loss_kernel<<<P_TOT, 32>>>(pred, target, mask, noise, (float*)d_out);
}

// round 13
// speedup vs baseline: 1.1348x; 1.1348x over previous
#include <cuda_runtime.h>
#include <stdint.h>

#define WW 2048
#define STR 8
#define NWW 255
#define P_TOT 32385          /* 127 * 255 */
#define MARGIN_F 1e-4f
#define WARPS_PER_BLK 2
#define NBLOCKS ((P_TOT + WARPS_PER_BLK - 1) / WARPS_PER_BLK)
#define FULL 0xffffffffu
#define NSLOT 32

__device__ double   g_loss_slot[NSLOT];   // zero-init; reset by finalizer
__device__ double   g_used_slot[NSLOT];
__device__ unsigned g_done = 0u;

// bank-conflict-free granule swizzle: 16B granule g -> g ^ ((g>>2)&7)
__device__ __forceinline__ int swz(int g) { return g ^ ((g >> 2) & 7); }

// sel iff sign(dt) != sign(dp): signbit XOR + the dt==0 self-pair case
__device__ __forceinline__ bool sel_pair(float dt, float dp) {
    return (((__float_as_uint(dt) ^ __float_as_uint(dp)) >> 31) != 0u)
           | (dt == 0.0f);
}

// ---------------------------------------------------------------------------
// TWO warps per block (64 threads): balances CTA-slot occupancy (vs 1-warp
// blocks, R12: 44.6% occ) against intra-block path imbalance (vs 8-warp
// blocks, R11: nearly every block carries a slow K>128 warp).
//   token = (noise_bits & 0xFFFFFF00) | elem_idx  (masked, < 0xFF000000)
//         =  0xFF000000 | elem_idx                (unmasked -> sorts last)
//   K <= 128: compact masked tokens, 128-wide sort (28 substeps, 4 regs).
//   K  > 128: in-register 256-wide sort (36 substeps, 8 regs).
// ---------------------------------------------------------------------------
__global__ __launch_bounds__(32 * WARPS_PER_BLK) void patch_loss_kernel(
    const float* __restrict__ pred,
    const float* __restrict__ target,
    const uint8_t* __restrict__ mask_raw,
    const float* __restrict__ noise,
    float* __restrict__ out)
{
    __shared__ float2   s_pt [WARPS_PER_BLK][256];   // swizzled (pred,target)
    __shared__ uint8_t  s_m  [WARPS_PER_BLK][256];
    __shared__ uint32_t s_tok[WARPS_PER_BLK][128];   // compacted tokens (path A)
    __shared__ float    s_blk_loss;
    __shared__ float    s_blk_cnt;

    const int wid  = threadIdx.x >> 5;
    const int lane = threadIdx.x & 31;

    if (threadIdx.x == 0) { s_blk_loss = 0.f; s_blk_cnt = 0.f; }
    __syncthreads();

    const int p = blockIdx.x * WARPS_PER_BLK + wid;
    if (p < P_TOT) {
        // ---- mask dtype detect on first 1KB (L2-resident for all blocks) ----
        int mode;
        {
            const uint32_t* w = (const uint32_t*)mask_raw;
            uint32_t acc_or = 0; bool gt1 = false;
            #pragma unroll
            for (int i = 0; i < 8; i++) {
                const uint32_t x = __ldg(w + lane + 32 * i);
                acc_or |= x; gt1 |= (x > 1u);
            }
            const unsigned bb = __ballot_sync(FULL, (acc_or & 0xFEFEFEFEu) != 0);
            const unsigned bg = __ballot_sync(FULL, gt1);
            mode = bb ? 1 : (bg ? 0 : 2);    // f32 : u8 : i32
        }

        const int pi = p / NWW;
        const int pj = p - pi * NWW;
        const int br = pi * STR;
        const int bc = pj * STR;

        const int e0    = lane << 3;             // this thread's 8 elements
        const int a     = lane >> 1;             // patch row
        const int gbase = (br + a) * WW + bc + ((lane & 1) << 3);

        // ---- vectorized loads ----
        const float4 p0 = __ldg((const float4*)(pred + gbase));
        const float4 p1 = __ldg((const float4*)(pred + gbase) + 1);
        const float4 t0 = __ldg((const float4*)(target + gbase));
        const float4 t1 = __ldg((const float4*)(target + gbase) + 1);

        // swizzled conflict-free STS.128: granule g = 4*lane + i
        {
            float4* base = (float4*)&s_pt[wid][0];
            const int g0 = lane << 2;
            base[swz(g0 + 0)] = make_float4(p0.x, t0.x, p0.y, t0.y);
            base[swz(g0 + 1)] = make_float4(p0.z, t0.z, p0.w, t0.w);
            base[swz(g0 + 2)] = make_float4(p1.x, t1.x, p1.y, t1.y);
            base[swz(g0 + 3)] = make_float4(p1.z, t1.z, p1.w, t1.w);
        }

        uint32_t mbits;                          // bit r = element e0+r masked
        if (mode == 0) {
            const uint2 mb = __ldg((const uint2*)(mask_raw + gbase));
            uint32_t b = 0;
            #pragma unroll
            for (int r = 0; r < 4; r++) b |= ((mb.x >> (8 * r)) & 1u) << r;
            #pragma unroll
            for (int r = 0; r < 4; r++) b |= ((mb.y >> (8 * r)) & 1u) << (4 + r);
            mbits = b;
        } else if (mode == 1) {
            const float4 m0 = __ldg((const float4*)((const float*)mask_raw + gbase));
            const float4 m1 = __ldg((const float4*)((const float*)mask_raw + gbase) + 1);
            mbits = (m0.x != 0.f) | ((m0.y != 0.f) << 1) | ((m0.z != 0.f) << 2) |
                    ((m0.w != 0.f) << 3) | ((m1.x != 0.f) << 4) | ((m1.y != 0.f) << 5) |
                    ((m1.z != 0.f) << 6) | ((m1.w != 0.f) << 7);
        } else {
            const uint4 m0 = __ldg((const uint4*)((const uint32_t*)mask_raw + gbase));
            const uint4 m1 = __ldg((const uint4*)((const uint32_t*)mask_raw + gbase) + 1);
            mbits = (m0.x != 0) | ((m0.y != 0) << 1) | ((m0.z != 0) << 2) |
                    ((m0.w != 0) << 3) | ((m1.x != 0) << 4) | ((m1.y != 0) << 5) |
                    ((m1.z != 0) << 6) | ((m1.w != 0) << 7);
        }

        const float4 n0 = __ldg((const float4*)(noise + (size_t)p * 256 + e0));
        const float4 n1 = __ldg((const float4*)(noise + (size_t)p * 256 + e0) + 1);
        const float nz[8] = {n0.x, n0.y, n0.z, n0.w, n1.x, n1.y, n1.z, n1.w};

        uint32_t tok[8];
        #pragma unroll
        for (int r = 0; r < 8; r++) {
            const uint32_t kb = __float_as_uint(nz[r]) & 0xFFFFFF00u;
            tok[r] = ((mbits >> r) & 1u) ? (kb | (uint32_t)(e0 + r))
                                         : (0xFF000000u | (uint32_t)(e0 + r));
        }

        // ---- ranks of masked elements (element order == 8*lane + r) ----
        const int cnt = __popc(mbits);
        int inc = cnt;
        #pragma unroll
        for (int o = 1; o < 32; o <<= 1) {
            const int t = __shfl_up_sync(FULL, inc, o);
            if (lane >= o) inc += t;
        }
        const int K = __shfl_sync(FULL, inc, 31);   // warp-uniform
        const bool pathA = (K <= 128);
        const int base = inc - cnt;

        // compaction with independent offsets
        #pragma unroll
        for (int r = 0; r < 8; r++) {
            if ((mbits >> r) & 1u) {
                const int off = base + __popc(mbits & ((1u << r) - 1u));
                s_m[wid][off] = (uint8_t)(e0 + r);
                if (pathA) s_tok[wid][off] = tok[r];
            }
        }
        if (pathA) {
            for (int v = K + lane; v < 128; v += 32)
                s_tok[wid][v] = 0xFFFFFFFFu;
        }
        __syncwarp();

        const float2* ptbase = &s_pt[wid][0];
        float loss = 0.f;
        int   hit  = 0;

        if (pathA) {
            // ==== 128-wide sort over positions v = 4*lane + r ====
            uint32_t t4[4];
            {
                const uint4 ld = *(const uint4*)&s_tok[wid][lane << 2];
                t4[0] = ld.x; t4[1] = ld.y; t4[2] = ld.z; t4[3] = ld.w;
            }
            #pragma unroll
            for (int k = 2; k <= 128; k <<= 1) {
                #pragma unroll
                for (int j = k >> 1; j >= 1; j >>= 1) {
                    if (j >= 4) {
                        const int jl = j >> 2;
                        const bool up = ((lane & (k >> 2)) == 0);
                        const bool tm = (up == ((lane & jl) == 0));
                        #pragma unroll
                        for (int r = 0; r < 4; r++) {
                            const uint32_t o = __shfl_xor_sync(FULL, t4[r], jl);
                            t4[r] = tm ? min(t4[r], o) : max(t4[r], o);
                        }
                    } else {
                        #pragma unroll
                        for (int r = 0; r < 4; r++) {
                            if ((r & j) == 0) {
                                const int r2 = r | j;
                                const bool up = (k < 4) ? ((r & k) == 0)
                                                        : ((lane & (k >> 2)) == 0);
                                const uint32_t A = t4[r], B = t4[r2];
                                t4[r]  = up ? min(A, B) : max(A, B);
                                t4[r2] = up ? max(A, B) : min(A, B);
                            }
                        }
                    }
                }
            }
            #pragma unroll
            for (int r = 0; r < 4; r++) {
                const int v = (lane << 2) + r;
                if (v < K) {
                    const int bI = (int)(t4[r] & 0xFFu);
                    const int aI = (int)s_m[wid][v];
                    const float2 A = ptbase[(swz(aI >> 1) << 1) | (aI & 1)];
                    const float2 B = ptbase[(swz(bI >> 1) << 1) | (bI & 1)];
                    const float dt = A.y - B.y;
                    const float dp = A.x - B.x + MARGIN_F;
                    if (sel_pair(dt, dp)) { hit++; loss += fabsf(dp); }
                }
            }
        } else {
            // ==== 256-wide sort over positions v = 8*lane + r ====
            #pragma unroll
            for (int k = 2; k <= 256; k <<= 1) {
                #pragma unroll
                for (int j = k >> 1; j >= 1; j >>= 1) {
                    if (j >= 8) {
                        const int jl = j >> 3;
                        const bool up = ((lane & (k >> 3)) == 0);
                        const bool tm = (up == ((lane & jl) == 0));
                        #pragma unroll
                        for (int r = 0; r < 8; r++) {
                            const uint32_t o = __shfl_xor_sync(FULL, tok[r], jl);
                            tok[r] = tm ? min(tok[r], o) : max(tok[r], o);
                        }
                    } else {
                        #pragma unroll
                        for (int r = 0; r < 8; r++) {
                            if ((r & j) == 0) {
                                const int r2 = r | j;
                                const bool up = (k < 8) ? ((r & k) == 0)
                                                        : ((lane & (k >> 3)) == 0);
                                const uint32_t A = tok[r], B = tok[r2];
                                tok[r]  = up ? min(A, B) : max(A, B);
                                tok[r2] = up ? max(A, B) : min(A, B);
                            }
                        }
                    }
                }
            }
            #pragma unroll
            for (int r = 0; r < 8; r++) {
                const int v = e0 + r;
                if (v < K) {
                    const int bI = (int)(tok[r] & 0xFFu);
                    const int aI = (int)s_m[wid][v];
                    const float2 A = ptbase[(swz(aI >> 1) << 1) | (aI & 1)];
                    const float2 B = ptbase[(swz(bI >> 1) << 1) | (bI & 1)];
                    const float dt = A.y - B.y;
                    const float dp = A.x - B.x + MARGIN_F;
                    if (sel_pair(dt, dp)) { hit++; loss += fabsf(dp); }
                }
            }
        }

        hit = __reduce_add_sync(FULL, hit);
        #pragma unroll
        for (int o = 16; o; o >>= 1)
            loss += __shfl_xor_sync(FULL, loss, o);
        if (lane == 0 && K > 0) {
            atomicAdd(&s_blk_loss, loss / (float)hit);
            atomicAdd(&s_blk_cnt, 1.0f);
        }
    }
    __syncthreads();

    // ---- block -> global accumulation; last block finalizes + resets ----
    if (threadIdx.x == 0) {
        const int slot = blockIdx.x & (NSLOT - 1);
        atomicAdd(&g_loss_slot[slot], (double)s_blk_loss);
        atomicAdd(&g_used_slot[slot], (double)s_blk_cnt);
        __threadfence();
        const unsigned ticket = atomicAdd(&g_done, 1u);
        if (ticket == (unsigned)(gridDim.x - 1)) {
            double ls = 0.0, us = 0.0;
            #pragma unroll
            for (int s = 0; s < NSLOT; s++) {
                ls += atomicAdd(&g_loss_slot[s], 0.0);
                us += atomicAdd(&g_used_slot[s], 0.0);
            }
            out[0] = (float)(ls / us);
            #pragma unroll
            for (int s = 0; s < NSLOT; s++) {   // reset for next graph replay
                g_loss_slot[s] = 0.0;
                g_used_slot[s] = 0.0;
            }
            __threadfence();
            g_done = 0u;
        }
    }
}

// ---------------------------------------------------------------------------
extern "C" void kernel_launch(void* const* d_in, const int* in_sizes, int n_in,
                              void* d_out, int out_size) {
    const float*   pred   = (const float*)d_in[0];
    const float*   target = (const float*)d_in[1];
    const uint8_t* mask   = (const uint8_t*)d_in[2];
    const float*   noise  = (const float*)d_in[3];

    patch_loss_kernel<<<NBLOCKS, 32 * WARPS_PER_BLK>>>(pred, target, mask, noise,
                                                       (float*)d_out);
}

// round 14
// speedup vs baseline: 1.2844x; 1.1319x over previous
#include <cuda_runtime.h>
#include <stdint.h>

#define WW 2048
#define STR 8
#define NWW 255
#define P_TOT 32385          /* 127 * 255 */
#define MARGIN_F 1e-4f
#define WARPS_PER_BLK 8
#define NBLOCKS ((P_TOT + WARPS_PER_BLK - 1) / WARPS_PER_BLK)
#define FULL 0xffffffffu

__device__ double   g_loss_sum = 0.0;
__device__ double   g_used     = 0.0;
__device__ unsigned g_done     = 0u;

// bank-conflict-free granule swizzle: 16B granule g -> g ^ ((g>>2)&7)
__device__ __forceinline__ int swz(int g) { return g ^ ((g >> 2) & 7); }

// sel iff sign(dt) != sign(dp): signbit XOR + the dt==0 self-pair case
__device__ __forceinline__ bool sel_pair(float dt, float dp) {
    return (((__float_as_uint(dt) ^ __float_as_uint(dp)) >> 31) != 0u)
           | (dt == 0.0f);
}

// ---------------------------------------------------------------------------
// One warp per patch (8 per block).
//   token = (noise_bits & 0xFFFFFF00) | elem_idx  (masked, < 0xFF000000)
//         =  0xFF000000 | elem_idx                (unmasked)
// K = #masked (warp-uniform, ~Bin(256,1/2)):
//   A:  K <= 128          : 128-wide sort of compacted tokens (28 substeps).
//   B': 128 < K <= 160    : sort-128 + sort-32(desc) + bitonic merge-256.
//   C:  K  > 160 (~3e-5)  : in-register 256-wide sort (36 substeps).
// ---------------------------------------------------------------------------
__global__ void patch_loss_kernel(
    const float* __restrict__ pred,
    const float* __restrict__ target,
    const uint8_t* __restrict__ mask_raw,
    const float* __restrict__ noise,
    float* __restrict__ out)
{
    __shared__ float2   s_pt [WARPS_PER_BLK][256];   // swizzled (pred,target)
    __shared__ uint8_t  s_m  [WARPS_PER_BLK][256];
    __shared__ uint32_t s_tok[WARPS_PER_BLK][256];   // compacted tokens
    __shared__ float    s_blk_loss;
    __shared__ float    s_blk_cnt;
    __shared__ int      s_mode;

    const int wid  = threadIdx.x >> 5;
    const int lane = threadIdx.x & 31;

    if (threadIdx.x == 0) { s_blk_loss = 0.f; s_blk_cnt = 0.f; }
    if (wid == 0) {
        // mask dtype detect on first 1KB (same L2 lines for every block)
        const uint32_t* w = (const uint32_t*)mask_raw;
        uint32_t acc_or = 0; bool gt1 = false;
        #pragma unroll
        for (int i = 0; i < 8; i++) {
            const uint32_t x = __ldg(w + lane + 32 * i);
            acc_or |= x; gt1 |= (x > 1u);
        }
        const unsigned bb = __ballot_sync(FULL, (acc_or & 0xFEFEFEFEu) != 0);
        const unsigned bg = __ballot_sync(FULL, gt1);
        if (lane == 0) s_mode = bb ? 1 : (bg ? 0 : 2);   // f32 : u8 : i32
    }
    __syncthreads();

    const int p = blockIdx.x * WARPS_PER_BLK + wid;
    if (p < P_TOT) {
        const int pi = p / NWW;
        const int pj = p - pi * NWW;
        const int br = pi * STR;
        const int bc = pj * STR;
        const int mode = s_mode;

        const int e0    = lane << 3;             // this thread's 8 elements
        const int a     = lane >> 1;             // patch row
        const int gbase = (br + a) * WW + bc + ((lane & 1) << 3);

        // ---- vectorized loads ----
        const float4 p0 = __ldg((const float4*)(pred + gbase));
        const float4 p1 = __ldg((const float4*)(pred + gbase) + 1);
        const float4 t0 = __ldg((const float4*)(target + gbase));
        const float4 t1 = __ldg((const float4*)(target + gbase) + 1);
        {
            float4* base = (float4*)&s_pt[wid][0];
            const int g0 = lane << 2;
            base[swz(g0 + 0)] = make_float4(p0.x, t0.x, p0.y, t0.y);
            base[swz(g0 + 1)] = make_float4(p0.z, t0.z, p0.w, t0.w);
            base[swz(g0 + 2)] = make_float4(p1.x, t1.x, p1.y, t1.y);
            base[swz(g0 + 3)] = make_float4(p1.z, t1.z, p1.w, t1.w);
        }

        uint32_t mbits;                          // bit r = element e0+r masked
        if (mode == 0) {
            const uint2 mb = __ldg((const uint2*)(mask_raw + gbase));
            uint32_t b = 0;
            #pragma unroll
            for (int r = 0; r < 4; r++) b |= ((mb.x >> (8 * r)) & 1u) << r;
            #pragma unroll
            for (int r = 0; r < 4; r++) b |= ((mb.y >> (8 * r)) & 1u) << (4 + r);
            mbits = b;
        } else if (mode == 1) {
            const float4 m0 = __ldg((const float4*)((const float*)mask_raw + gbase));
            const float4 m1 = __ldg((const float4*)((const float*)mask_raw + gbase) + 1);
            mbits = (m0.x != 0.f) | ((m0.y != 0.f) << 1) | ((m0.z != 0.f) << 2) |
                    ((m0.w != 0.f) << 3) | ((m1.x != 0.f) << 4) | ((m1.y != 0.f) << 5) |
                    ((m1.z != 0.f) << 6) | ((m1.w != 0.f) << 7);
        } else {
            const uint4 m0 = __ldg((const uint4*)((const uint32_t*)mask_raw + gbase));
            const uint4 m1 = __ldg((const uint4*)((const uint32_t*)mask_raw + gbase) + 1);
            mbits = (m0.x != 0) | ((m0.y != 0) << 1) | ((m0.z != 0) << 2) |
                    ((m0.w != 0) << 3) | ((m1.x != 0) << 4) | ((m1.y != 0) << 5) |
                    ((m1.z != 0) << 6) | ((m1.w != 0) << 7);
        }

        const float4 n0 = __ldg((const float4*)(noise + (size_t)p * 256 + e0));
        const float4 n1 = __ldg((const float4*)(noise + (size_t)p * 256 + e0) + 1);
        const float nz[8] = {n0.x, n0.y, n0.z, n0.w, n1.x, n1.y, n1.z, n1.w};

        uint32_t tok[8];
        #pragma unroll
        for (int r = 0; r < 8; r++) {
            const uint32_t kb = __float_as_uint(nz[r]) & 0xFFFFFF00u;
            tok[r] = ((mbits >> r) & 1u) ? (kb | (uint32_t)(e0 + r))
                                         : (0xFF000000u | (uint32_t)(e0 + r));
        }

        // ---- ranks of masked elements (element order == 8*lane + r) ----
        const int cnt = __popc(mbits);
        int inc = cnt;
        #pragma unroll
        for (int o = 1; o < 32; o <<= 1) {
            const int t = __shfl_up_sync(FULL, inc, o);
            if (lane >= o) inc += t;
        }
        const int K = __shfl_sync(FULL, inc, 31);   // warp-uniform
        const bool pathA  = (K <= 128);
        const bool pathBp = (K > 128) && (K <= 160);
        const int base = inc - cnt;

        // compaction (independent offsets); tokens to smem for paths A and B'
        #pragma unroll
        for (int r = 0; r < 8; r++) {
            if ((mbits >> r) & 1u) {
                const int off = base + __popc(mbits & ((1u << r) - 1u));
                s_m[wid][off] = (uint8_t)(e0 + r);
                if (pathA | pathBp) s_tok[wid][off] = tok[r];
            }
        }
        if (pathA) {
            for (int v = K + lane; v < 128; v += 32) s_tok[wid][v] = 0xFFFFFFFFu;
        } else if (pathBp) {
            for (int v = K + lane; v < 160; v += 32) s_tok[wid][v] = 0xFFFFFFFFu;
        }
        __syncwarp();

        const float2* ptbase = &s_pt[wid][0];
        float loss = 0.f;
        int   hit  = 0;

        if (pathA | pathBp) {
            // ==== shared 128-wide sort over positions v = 4*lane + r ====
            uint32_t t4[4];
            {
                const uint4 ld = *(const uint4*)&s_tok[wid][lane << 2];
                t4[0] = ld.x; t4[1] = ld.y; t4[2] = ld.z; t4[3] = ld.w;
            }
            #pragma unroll
            for (int k = 2; k <= 128; k <<= 1) {
                #pragma unroll
                for (int j = k >> 1; j >= 1; j >>= 1) {
                    if (j >= 4) {
                        const int jl = j >> 2;
                        const bool up = ((lane & (k >> 2)) == 0);
                        const bool tm = (up == ((lane & jl) == 0));
                        #pragma unroll
                        for (int r = 0; r < 4; r++) {
                            const uint32_t o = __shfl_xor_sync(FULL, t4[r], jl);
                            t4[r] = tm ? min(t4[r], o) : max(t4[r], o);
                        }
                    } else {
                        #pragma unroll
                        for (int r = 0; r < 4; r++) {
                            if ((r & j) == 0) {
                                const int r2 = r | j;
                                const bool up = (k < 4) ? ((r & k) == 0)
                                                        : ((lane & (k >> 2)) == 0);
                                const uint32_t A = t4[r], B = t4[r2];
                                t4[r]  = up ? min(A, B) : max(A, B);
                                t4[r2] = up ? max(A, B) : min(A, B);
                            }
                        }
                    }
                }
            }

            if (pathA) {
                // ==== epilogue A: 4 positions/thread ====
                #pragma unroll
                for (int r = 0; r < 4; r++) {
                    const int v = (lane << 2) + r;
                    if (v < K) {
                        const int bI = (int)(t4[r] & 0xFFu);
                        const int aI = (int)s_m[wid][v];
                        const float2 A = ptbase[(swz(aI >> 1) << 1) | (aI & 1)];
                        const float2 B = ptbase[(swz(bI >> 1) << 1) | (bI & 1)];
                        const float dt = A.y - B.y;
                        const float dp = A.x - B.x + MARGIN_F;
                        if (sel_pair(dt, dp)) { hit++; loss += fabsf(dp); }
                    }
                }
            } else {
                // ==== B': second half (ranks 128..K-1, <=32 tokens) ====
                uint32_t s = s_tok[wid][128 + lane];      // pads 0xFFFFFFFF
                // ascending 32-wide sort
                #pragma unroll
                for (int k = 2; k <= 32; k <<= 1) {
                    #pragma unroll
                    for (int j = k >> 1; j >= 1; j >>= 1) {
                        const uint32_t o = __shfl_xor_sync(FULL, s, j);
                        const bool tm = (((lane & k) == 0) == ((lane & j) == 0));
                        s = tm ? min(s, o) : max(s, o);
                    }
                }
                // reverse -> descending (pads first, tokens descending last)
                s = __shfl_sync(FULL, s, 31 ^ lane);

                // write sorted-128 back, reload lane-major
                __syncwarp();
                *(uint4*)&s_tok[wid][lane << 2] =
                    make_uint4(t4[0], t4[1], t4[2], t4[3]);
                __syncwarp();

                // merged layout v = lane + 32*r:
                //  r=0..3 : ascending 128 ; r=4..6 : max-pad ; r=7 : desc run
                uint32_t t8[8];
                #pragma unroll
                for (int r = 0; r < 4; r++) t8[r] = s_tok[wid][lane + 32 * r];
                t8[4] = 0xFFFFFFFFu; t8[5] = 0xFFFFFFFFu; t8[6] = 0xFFFFFFFFu;
                t8[7] = s;

                // bitonic merge of 256, ascending (all substeps keep-min-low)
                #pragma unroll
                for (int r = 0; r < 4; r++) {           // j = 128
                    const uint32_t A = t8[r], B = t8[r + 4];
                    t8[r] = min(A, B); t8[r + 4] = max(A, B);
                }
                #pragma unroll
                for (int r = 0; r < 8; r++) {           // j = 64
                    if ((r & 2) == 0) {
                        const int r2 = r | 2;
                        const uint32_t A = t8[r], B = t8[r2];
                        t8[r] = min(A, B); t8[r2] = max(A, B);
                    }
                }
                #pragma unroll
                for (int r = 0; r < 8; r += 2) {        // j = 32
                    const uint32_t A = t8[r], B = t8[r + 1];
                    t8[r] = min(A, B); t8[r + 1] = max(A, B);
                }
                #pragma unroll
                for (int j = 16; j >= 1; j >>= 1) {     // j = 16..1 cross-lane
                    const bool tm = ((lane & j) == 0);
                    #pragma unroll
                    for (int r = 0; r < 8; r++) {
                        const uint32_t o = __shfl_xor_sync(FULL, t8[r], j);
                        t8[r] = tm ? min(t8[r], o) : max(t8[r], o);
                    }
                }

                // ==== epilogue B': tokens at positions 0..K-1, v = lane+32r ====
                #pragma unroll
                for (int r = 0; r < 8; r++) {
                    const int v = lane + 32 * r;
                    if (v < K) {
                        const int bI = (int)(t8[r] & 0xFFu);
                        const int aI = (int)s_m[wid][v];
                        const float2 A = ptbase[(swz(aI >> 1) << 1) | (aI & 1)];
                        const float2 B = ptbase[(swz(bI >> 1) << 1) | (bI & 1)];
                        const float dt = A.y - B.y;
                        const float dp = A.x - B.x + MARGIN_F;
                        if (sel_pair(dt, dp)) { hit++; loss += fabsf(dp); }
                    }
                }
            }
        } else {
            // ==== path C (K > 160, ~1 patch/run): 256-wide in-register ====
            #pragma unroll
            for (int k = 2; k <= 256; k <<= 1) {
                #pragma unroll
                for (int j = k >> 1; j >= 1; j >>= 1) {
                    if (j >= 8) {
                        const int jl = j >> 3;
                        const bool up = ((lane & (k >> 3)) == 0);
                        const bool tm = (up == ((lane & jl) == 0));
                        #pragma unroll
                        for (int r = 0; r < 8; r++) {
                            const uint32_t o = __shfl_xor_sync(FULL, tok[r], jl);
                            tok[r] = tm ? min(tok[r], o) : max(tok[r], o);
                        }
                    } else {
                        #pragma unroll
                        for (int r = 0; r < 8; r++) {
                            if ((r & j) == 0) {
                                const int r2 = r | j;
                                const bool up = (k < 8) ? ((r & k) == 0)
                                                        : ((lane & (k >> 3)) == 0);
                                const uint32_t A = tok[r], B = tok[r2];
                                tok[r]  = up ? min(A, B) : max(A, B);
                                tok[r2] = up ? max(A, B) : min(A, B);
                            }
                        }
                    }
                }
            }
            #pragma unroll
            for (int r = 0; r < 8; r++) {
                const int v = e0 + r;
                if (v < K) {
                    const int bI = (int)(tok[r] & 0xFFu);
                    const int aI = (int)s_m[wid][v];
                    const float2 A = ptbase[(swz(aI >> 1) << 1) | (aI & 1)];
                    const float2 B = ptbase[(swz(bI >> 1) << 1) | (bI & 1)];
                    const float dt = A.y - B.y;
                    const float dp = A.x - B.x + MARGIN_F;
                    if (sel_pair(dt, dp)) { hit++; loss += fabsf(dp); }
                }
            }
        }

        hit = __reduce_add_sync(FULL, hit);
        #pragma unroll
        for (int o = 16; o; o >>= 1)
            loss += __shfl_xor_sync(FULL, loss, o);
        if (lane == 0 && K > 0) {
            atomicAdd(&s_blk_loss, loss / (float)hit);
            atomicAdd(&s_blk_cnt, 1.0f);
        }
    }
    __syncthreads();

    // ---- block -> global accumulation; last block finalizes + resets ----
    if (threadIdx.x == 0) {
        atomicAdd(&g_loss_sum, (double)s_blk_loss);
        atomicAdd(&g_used,     (double)s_blk_cnt);
        __threadfence();
        const unsigned ticket = atomicAdd(&g_done, 1u);
        if (ticket == (unsigned)(gridDim.x - 1)) {
            const double ls = atomicAdd(&g_loss_sum, 0.0);
            const double us = atomicAdd(&g_used, 0.0);
            out[0] = (float)(ls / us);
            g_loss_sum = 0.0;              // reset for next graph replay
            g_used     = 0.0;
            __threadfence();
            g_done = 0u;
        }
    }
}

// ---------------------------------------------------------------------------
extern "C" void kernel_launch(void* const* d_in, const int* in_sizes, int n_in,
                              void* d_out, int out_size) {
    const float*   pred   = (const float*)d_in[0];
    const float*   target = (const float*)d_in[1];
    const uint8_t* mask   = (const uint8_t*)d_in[2];
    const float*   noise  = (const float*)d_in[3];

    patch_loss_kernel<<<NBLOCKS, 256>>>(pred, target, mask, noise, (float*)d_out);
}

// round 15
// speedup vs baseline: 1.3362x; 1.0403x over previous
#include <cuda_runtime.h>
#include <stdint.h>

#define WW 2048
#define STR 8
#define NWW 255
#define P_TOT 32385          /* 127 * 255 */
#define MARGIN_F 1e-4f
#define WARPS_PER_BLK 8
#define NBLOCKS ((P_TOT + WARPS_PER_BLK - 1) / WARPS_PER_BLK)
#define FULL 0xffffffffu

__device__ double   g_loss_sum = 0.0;
__device__ double   g_used     = 0.0;
__device__ unsigned g_done     = 0u;

// bank-conflict-free granule swizzle: 16B granule g -> g ^ ((g>>2)&7)
__device__ __forceinline__ int swz(int g) { return g ^ ((g >> 2) & 7); }

// sel iff sign(dt) != sign(dp): signbit XOR + the dt==0 self-pair case
__device__ __forceinline__ bool sel_pair(float dt, float dp) {
    return (((__float_as_uint(dt) ^ __float_as_uint(dp)) >> 31) != 0u)
           | (dt == 0.0f);
}

// ---------------------------------------------------------------------------
// One warp per patch (8 per block).
//   token = (noise_bits & 0xFFFFFF00) | elem_idx  (masked, < 0xFF000000)
//         =  0xFF000000 | elem_idx                (unmasked)
// K = #masked (warp-uniform, ~Bin(256,1/2)):
//   A:  K <= 128          : 128-wide sort of compacted tokens (28 substeps).
//   B': 128 < K <= 160    : sort-128 + sort-32(desc) + FOLDED bitonic merge
//                           (pads/known-order exchanges removed; only the 5
//                           register rows holding positions < 160 are merged).
//   C:  K  > 160 (~3e-5)  : in-register 256-wide sort (36 substeps).
// ---------------------------------------------------------------------------
__global__ void patch_loss_kernel(
    const float* __restrict__ pred,
    const float* __restrict__ target,
    const uint8_t* __restrict__ mask_raw,
    const float* __restrict__ noise,
    float* __restrict__ out)
{
    __shared__ float2   s_pt [WARPS_PER_BLK][256];   // swizzled (pred,target)
    __shared__ uint8_t  s_m  [WARPS_PER_BLK][256];
    __shared__ uint32_t s_tok[WARPS_PER_BLK][256];   // compacted tokens
    __shared__ float    s_blk_loss;
    __shared__ float    s_blk_cnt;
    __shared__ int      s_mode;

    const int wid  = threadIdx.x >> 5;
    const int lane = threadIdx.x & 31;

    if (threadIdx.x == 0) { s_blk_loss = 0.f; s_blk_cnt = 0.f; }
    if (wid == 0) {
        // mask dtype detect on first 1KB (same L2 lines for every block)
        const uint32_t* w = (const uint32_t*)mask_raw;
        uint32_t acc_or = 0; bool gt1 = false;
        #pragma unroll
        for (int i = 0; i < 8; i++) {
            const uint32_t x = __ldg(w + lane + 32 * i);
            acc_or |= x; gt1 |= (x > 1u);
        }
        const unsigned bb = __ballot_sync(FULL, (acc_or & 0xFEFEFEFEu) != 0);
        const unsigned bg = __ballot_sync(FULL, gt1);
        if (lane == 0) s_mode = bb ? 1 : (bg ? 0 : 2);   // f32 : u8 : i32
    }
    __syncthreads();

    const int p = blockIdx.x * WARPS_PER_BLK + wid;
    if (p < P_TOT) {
        const int pi = p / NWW;
        const int pj = p - pi * NWW;
        const int br = pi * STR;
        const int bc = pj * STR;
        const int mode = s_mode;

        const int e0    = lane << 3;             // this thread's 8 elements
        const int a     = lane >> 1;             // patch row
        const int gbase = (br + a) * WW + bc + ((lane & 1) << 3);

        // ---- vectorized loads ----
        const float4 p0 = __ldg((const float4*)(pred + gbase));
        const float4 p1 = __ldg((const float4*)(pred + gbase) + 1);
        const float4 t0 = __ldg((const float4*)(target + gbase));
        const float4 t1 = __ldg((const float4*)(target + gbase) + 1);
        {
            float4* base = (float4*)&s_pt[wid][0];
            const int g0 = lane << 2;
            base[swz(g0 + 0)] = make_float4(p0.x, t0.x, p0.y, t0.y);
            base[swz(g0 + 1)] = make_float4(p0.z, t0.z, p0.w, t0.w);
            base[swz(g0 + 2)] = make_float4(p1.x, t1.x, p1.y, t1.y);
            base[swz(g0 + 3)] = make_float4(p1.z, t1.z, p1.w, t1.w);
        }

        uint32_t mbits;                          // bit r = element e0+r masked
        if (mode == 0) {
            const uint2 mb = __ldg((const uint2*)(mask_raw + gbase));
            uint32_t b = 0;
            #pragma unroll
            for (int r = 0; r < 4; r++) b |= ((mb.x >> (8 * r)) & 1u) << r;
            #pragma unroll
            for (int r = 0; r < 4; r++) b |= ((mb.y >> (8 * r)) & 1u) << (4 + r);
            mbits = b;
        } else if (mode == 1) {
            const float4 m0 = __ldg((const float4*)((const float*)mask_raw + gbase));
            const float4 m1 = __ldg((const float4*)((const float*)mask_raw + gbase) + 1);
            mbits = (m0.x != 0.f) | ((m0.y != 0.f) << 1) | ((m0.z != 0.f) << 2) |
                    ((m0.w != 0.f) << 3) | ((m1.x != 0.f) << 4) | ((m1.y != 0.f) << 5) |
                    ((m1.z != 0.f) << 6) | ((m1.w != 0.f) << 7);
        } else {
            const uint4 m0 = __ldg((const uint4*)((const uint32_t*)mask_raw + gbase));
            const uint4 m1 = __ldg((const uint4*)((const uint32_t*)mask_raw + gbase) + 1);
            mbits = (m0.x != 0) | ((m0.y != 0) << 1) | ((m0.z != 0) << 2) |
                    ((m0.w != 0) << 3) | ((m1.x != 0) << 4) | ((m1.y != 0) << 5) |
                    ((m1.z != 0) << 6) | ((m1.w != 0) << 7);
        }

        const float4 n0 = __ldg((const float4*)(noise + (size_t)p * 256 + e0));
        const float4 n1 = __ldg((const float4*)(noise + (size_t)p * 256 + e0) + 1);
        const float nz[8] = {n0.x, n0.y, n0.z, n0.w, n1.x, n1.y, n1.z, n1.w};

        uint32_t tok[8];
        #pragma unroll
        for (int r = 0; r < 8; r++) {
            const uint32_t kb = __float_as_uint(nz[r]) & 0xFFFFFF00u;
            tok[r] = ((mbits >> r) & 1u) ? (kb | (uint32_t)(e0 + r))
                                         : (0xFF000000u | (uint32_t)(e0 + r));
        }

        // ---- ranks of masked elements (element order == 8*lane + r) ----
        const int cnt = __popc(mbits);
        int inc = cnt;
        #pragma unroll
        for (int o = 1; o < 32; o <<= 1) {
            const int t = __shfl_up_sync(FULL, inc, o);
            if (lane >= o) inc += t;
        }
        const int K = __shfl_sync(FULL, inc, 31);   // warp-uniform
        const bool pathA  = (K <= 128);
        const bool pathBp = (K > 128) && (K <= 160);
        const int base = inc - cnt;

        // compaction (independent offsets); tokens to smem for paths A and B'
        #pragma unroll
        for (int r = 0; r < 8; r++) {
            if ((mbits >> r) & 1u) {
                const int off = base + __popc(mbits & ((1u << r) - 1u));
                s_m[wid][off] = (uint8_t)(e0 + r);
                if (pathA | pathBp) s_tok[wid][off] = tok[r];
            }
        }
        if (pathA) {
            for (int v = K + lane; v < 128; v += 32) s_tok[wid][v] = 0xFFFFFFFFu;
        } else if (pathBp) {
            for (int v = K + lane; v < 160; v += 32) s_tok[wid][v] = 0xFFFFFFFFu;
        }
        __syncwarp();

        const float2* ptbase = &s_pt[wid][0];
        float loss = 0.f;
        int   hit  = 0;

        if (pathA | pathBp) {
            // ==== shared 128-wide sort over positions v = 4*lane + r ====
            uint32_t t4[4];
            {
                const uint4 ld = *(const uint4*)&s_tok[wid][lane << 2];
                t4[0] = ld.x; t4[1] = ld.y; t4[2] = ld.z; t4[3] = ld.w;
            }
            #pragma unroll
            for (int k = 2; k <= 128; k <<= 1) {
                #pragma unroll
                for (int j = k >> 1; j >= 1; j >>= 1) {
                    if (j >= 4) {
                        const int jl = j >> 2;
                        const bool up = ((lane & (k >> 2)) == 0);
                        const bool tm = (up == ((lane & jl) == 0));
                        #pragma unroll
                        for (int r = 0; r < 4; r++) {
                            const uint32_t o = __shfl_xor_sync(FULL, t4[r], jl);
                            t4[r] = tm ? min(t4[r], o) : max(t4[r], o);
                        }
                    } else {
                        #pragma unroll
                        for (int r = 0; r < 4; r++) {
                            if ((r & j) == 0) {
                                const int r2 = r | j;
                                const bool up = (k < 4) ? ((r & k) == 0)
                                                        : ((lane & (k >> 2)) == 0);
                                const uint32_t A = t4[r], B = t4[r2];
                                t4[r]  = up ? min(A, B) : max(A, B);
                                t4[r2] = up ? max(A, B) : min(A, B);
                            }
                        }
                    }
                }
            }

            if (pathA) {
                // ==== epilogue A: 4 positions/thread ====
                #pragma unroll
                for (int r = 0; r < 4; r++) {
                    const int v = (lane << 2) + r;
                    if (v < K) {
                        const int bI = (int)(t4[r] & 0xFFu);
                        const int aI = (int)s_m[wid][v];
                        const float2 A = ptbase[(swz(aI >> 1) << 1) | (aI & 1)];
                        const float2 B = ptbase[(swz(bI >> 1) << 1) | (bI & 1)];
                        const float dt = A.y - B.y;
                        const float dp = A.x - B.x + MARGIN_F;
                        if (sel_pair(dt, dp)) { hit++; loss += fabsf(dp); }
                    }
                }
            } else {
                // ==== B': second half (ranks 128..K-1, <=32 tokens) ====
                uint32_t s = s_tok[wid][128 + lane];      // pads 0xFFFFFFFF
                // ascending 32-wide sort
                #pragma unroll
                for (int k = 2; k <= 32; k <<= 1) {
                    #pragma unroll
                    for (int j = k >> 1; j >= 1; j >>= 1) {
                        const uint32_t o = __shfl_xor_sync(FULL, s, j);
                        const bool tm = (((lane & k) == 0) == ((lane & j) == 0));
                        s = tm ? min(s, o) : max(s, o);
                    }
                }
                // reverse -> descending (pads first, tokens descending last)
                s = __shfl_sync(FULL, s, 31 ^ lane);

                // write sorted-128 back, reload lane-major
                __syncwarp();
                *(uint4*)&s_tok[wid][lane << 2] =
                    make_uint4(t4[0], t4[1], t4[2], t4[3]);
                __syncwarp();

                // lane-major rows a_r = sorted[lane + 32r]; full 256 sequence
                // [asc-128 | pad,pad,pad | desc-32] is bitonic. r-level merge
                // steps with pads (=UINT_MAX) and a0<a1<a2<a3 folded out:
                uint32_t t8[5];
                #pragma unroll
                for (int r = 0; r < 4; r++) t8[r] = s_tok[wid][lane + 32 * r];

                // j=128: only pair (r3, s-row) does work
                const uint32_t n3 = min(t8[3], s);
                const uint32_t n7 = max(t8[3], s);
                // j=64: only pair (r1, n3) does work (n7 row pairs with pad)
                const uint32_t c1 = min(t8[1], n3);
                const uint32_t c3 = max(t8[1], n3);
                // j=32: pairs (r0,c1), (r2,c3); n7 moves into row 4
                t8[1] = max(t8[0], c1);
                t8[0] = min(t8[0], c1);
                t8[3] = max(t8[2], c3);
                t8[2] = min(t8[2], c3);
                t8[4] = n7;

                // j=16..1: intra-row; rows 5..7 (positions >=160 >= K) dropped
                #pragma unroll
                for (int j = 16; j >= 1; j >>= 1) {
                    const bool tm = ((lane & j) == 0);
                    #pragma unroll
                    for (int r = 0; r < 5; r++) {
                        const uint32_t o = __shfl_xor_sync(FULL, t8[r], j);
                        t8[r] = tm ? min(t8[r], o) : max(t8[r], o);
                    }
                }

                // ==== epilogue B': positions v = lane+32r, r < 5 ====
                #pragma unroll
                for (int r = 0; r < 5; r++) {
                    const int v = lane + 32 * r;
                    if (v < K) {
                        const int bI = (int)(t8[r] & 0xFFu);
                        const int aI = (int)s_m[wid][v];
                        const float2 A = ptbase[(swz(aI >> 1) << 1) | (aI & 1)];
                        const float2 B = ptbase[(swz(bI >> 1) << 1) | (bI & 1)];
                        const float dt = A.y - B.y;
                        const float dp = A.x - B.x + MARGIN_F;
                        if (sel_pair(dt, dp)) { hit++; loss += fabsf(dp); }
                    }
                }
            }
        } else {
            // ==== path C (K > 160, ~1 patch/run): 256-wide in-register ====
            #pragma unroll
            for (int k = 2; k <= 256; k <<= 1) {
                #pragma unroll
                for (int j = k >> 1; j >= 1; j >>= 1) {
                    if (j >= 8) {
                        const int jl = j >> 3;
                        const bool up = ((lane & (k >> 3)) == 0);
                        const bool tm = (up == ((lane & jl) == 0));
                        #pragma unroll
                        for (int r = 0; r < 8; r++) {
                            const uint32_t o = __shfl_xor_sync(FULL, tok[r], jl);
                            tok[r] = tm ? min(tok[r], o) : max(tok[r], o);
                        }
                    } else {
                        #pragma unroll
                        for (int r = 0; r < 8; r++) {
                            if ((r & j) == 0) {
                                const int r2 = r | j;
                                const bool up = (k < 8) ? ((r & k) == 0)
                                                        : ((lane & (k >> 3)) == 0);
                                const uint32_t A = tok[r], B = tok[r2];
                                tok[r]  = up ? min(A, B) : max(A, B);
                                tok[r2] = up ? max(A, B) : min(A, B);
                            }
                        }
                    }
                }
            }
            #pragma unroll
            for (int r = 0; r < 8; r++) {
                const int v = e0 + r;
                if (v < K) {
                    const int bI = (int)(tok[r] & 0xFFu);
                    const int aI = (int)s_m[wid][v];
                    const float2 A = ptbase[(swz(aI >> 1) << 1) | (aI & 1)];
                    const float2 B = ptbase[(swz(bI >> 1) << 1) | (bI & 1)];
                    const float dt = A.y - B.y;
                    const float dp = A.x - B.x + MARGIN_F;
                    if (sel_pair(dt, dp)) { hit++; loss += fabsf(dp); }
                }
            }
        }

        hit = __reduce_add_sync(FULL, hit);
        #pragma unroll
        for (int o = 16; o; o >>= 1)
            loss += __shfl_xor_sync(FULL, loss, o);
        if (lane == 0 && K > 0) {
            atomicAdd(&s_blk_loss, loss / (float)hit);
            atomicAdd(&s_blk_cnt, 1.0f);
        }
    }
    __syncthreads();

    // ---- block -> global accumulation; last block finalizes + resets ----
    if (threadIdx.x == 0) {
        atomicAdd(&g_loss_sum, (double)s_blk_loss);
        atomicAdd(&g_used,     (double)s_blk_cnt);
        __threadfence();
        const unsigned ticket = atomicAdd(&g_done, 1u);
        if (ticket == (unsigned)(gridDim.x - 1)) {
            const double ls = atomicAdd(&g_loss_sum, 0.0);
            const double us = atomicAdd(&g_used, 0.0);
            out[0] = (float)(ls / us);
            g_loss_sum = 0.0;              // reset for next graph replay
            g_used     = 0.0;
            __threadfence();
            g_done = 0u;
        }
    }
}

// ---------------------------------------------------------------------------
extern "C" void kernel_launch(void* const* d_in, const int* in_sizes, int n_in,
                              void* d_out, int out_size) {
    const float*   pred   = (const float*)d_in[0];
    const float*   target = (const float*)d_in[1];
    const uint8_t* mask   = (const uint8_t*)d_in[2];
    const float*   noise  = (const float*)d_in[3];

    patch_loss_kernel<<<NBLOCKS, 256>>>(pred, target, mask, noise, (float*)d_out);
}